// round 15
// baseline (speedup 1.0000x reference)
#include <cuda_runtime.h>
#include <cuda_fp16.h>
#include <cstdint>

#define NMAX 100000
#define NWORDS 50000
#define EMAX 500000
#define IN_DIM 256
#define OUT_DIM 128

// ---- scratch (static device globals; no allocation) ----
__device__ __half   g_z[(size_t)NMAX * OUT_DIM];   // fc output z [N,128] (fp16)
__device__ float    g_s1[NMAX];                    // z . a1
__device__ float    g_s2[NMAX];                    // z . a2
__device__ unsigned g_cnt[NWORDS];                 // per-dst edge counts
__device__ unsigned g_cnt2[NWORDS];                // scatter cursors
__device__ unsigned g_off[NWORDS + 1];             // CSR offsets
__device__ int      g_esrc[EMAX];                  // grouped edge src ids
__device__ float    g_eval[EMAX];                  // grouped edge scores
// pre-converted B (fp16) in swizzled tile layout: [kchunk][128 rows x 64 B]
__device__ __align__(16) uint8_t g_bhi[8 * 8192];

#define SCAN_BLOCKS ((NWORDS + 1023) / 1024)       // 49
__device__ unsigned g_bsum[SCAN_BLOCKS];

__device__ __forceinline__ uint32_t smem_u32(const void* p) {
    uint32_t a;
    asm("{ .reg .u64 t; cvta.to.shared.u64 t, %1; cvt.u32.u64 %0, t; }" : "=r"(a) : "l"(p));
    return a;
}
__device__ __forceinline__ void ldm_x4(uint32_t* r, uint32_t addr) {
    asm volatile("ldmatrix.sync.aligned.m8n8.x4.shared.b16 {%0,%1,%2,%3}, [%4];"
                 : "=r"(r[0]), "=r"(r[1]), "=r"(r[2]), "=r"(r[3]) : "r"(addr));
}
__device__ __forceinline__ void mma_fp16(float* c, const uint32_t* a, const uint32_t* b) {
    asm volatile(
        "mma.sync.aligned.m16n8k16.row.col.f32.f16.f16.f32 "
        "{%0,%1,%2,%3}, {%4,%5,%6,%7}, {%8,%9}, {%0,%1,%2,%3};"
        : "+f"(c[0]), "+f"(c[1]), "+f"(c[2]), "+f"(c[3])
        : "r"(a[0]), "r"(a[1]), "r"(a[2]), "r"(a[3]), "r"(b[0]), "r"(b[1]));
}
__device__ __forceinline__ uint32_t pack2h(float a, float b) {
    __half2 t = __floats2half2_rn(a, b);
    return *reinterpret_cast<uint32_t*>(&t);
}
// tile byte offset: row pitch 64B (32 fp16), 16B chunks xor-swizzled
__device__ __forceinline__ uint32_t tile_off(uint32_t row, uint32_t chunk) {
    return row * 64u + ((chunk ^ ((row >> 1) & 3u)) << 4);
}
// gather 4 fp32 cols from fp16 z row
__device__ __forceinline__ float4 ldz4(int s, int lane) {
    uint2 q = __ldg((const uint2*)&g_z[(size_t)s * OUT_DIM + lane * 4]);
    float2 f0 = __half22float2(*(__half2*)&q.x);
    float2 f1 = __half22float2(*(__half2*)&q.y);
    return make_float4(f0.x, f0.y, f1.x, f1.y);
}

// ---- side-stream init: zero counters ----
__global__ __launch_bounds__(256) void init_cnt_kernel() {
    int i = blockIdx.x * blockDim.x + threadIdx.x;
    if (i < NWORDS) { g_cnt[i] = 0u; g_cnt2[i] = 0u; }
}

// ---- main-stream: one-time B fp16 convert into swizzled layout ----
__global__ __launch_bounds__(256) void convert_b_kernel(const float* __restrict__ B) {
    int i = blockIdx.x * blockDim.x + threadIdx.x;   // 0..32767
    if (i >= 128 * 256) return;
    int row = i >> 8, col = i & 255;
    int kc = col >> 5, c = col & 31;
    uint32_t off = (uint32_t)kc * 8192u + tile_off((uint32_t)row, (uint32_t)(c >> 3)) + (c & 7) * 2;
    *(__half*)(g_bhi + off) = __float2half_rn(B[i]);
}

// ==========================================================================
// fp16 single-product GEMM via mma.sync: z = fp16(A) @ fp16(B)^T, fp32 acc.
// z stored as fp16; s1/s2 from fp32 acc via smem reduction (no atomics).
// ==========================================================================
__global__ void __launch_bounds__(256, 2)
gemm_mma(const float* __restrict__ A, const float* __restrict__ Wa, int M)
{
    __shared__ __align__(128) uint8_t sA[128 * 64];
    __shared__ __align__(128) uint8_t sB[128 * 64];

    const int tid  = threadIdx.x;
    const int lane = tid & 31;
    const int w    = tid >> 5;
    const int wm   = w & 3;
    const int wn   = w >> 2;
    const int block_m = blockIdx.x * 128;
    int rows_valid = M - block_m; if (rows_valid > 128) rows_valid = 128;

    const uint32_t uA = smem_u32(sA);
    const uint32_t uB = smem_u32(sB);

    const uint32_t a_row  = wm * 32u + (lane & 15);
    const uint32_t a_half = (uint32_t)lane >> 4;
    const uint32_t a_sw   = (a_row >> 1) & 3u;
    const uint32_t b_row  = wn * 64u + (lane & 7) + (((uint32_t)lane >> 4) << 3);
    const uint32_t b_half = ((uint32_t)lane >> 3) & 1u;
    const uint32_t b_sw   = (b_row >> 1) & 3u;

    const int r0 = tid >> 2,         c0 = tid & 3;
    const int r1 = (tid + 256) >> 2, c1 = (tid + 256) & 3;
    const uint32_t doff0 = tile_off((uint32_t)r0, (uint32_t)c0);
    const uint32_t doff1 = tile_off((uint32_t)r1, (uint32_t)c1);

    float acc[2][8][4];
#pragma unroll
    for (int i = 0; i < 2; i++)
#pragma unroll
        for (int j = 0; j < 8; j++)
#pragma unroll
            for (int r = 0; r < 4; r++) acc[i][j][r] = 0.0f;

    float4 pv[4];
    {
        pv[0] = pv[1] = pv[2] = pv[3] = make_float4(0.f, 0.f, 0.f, 0.f);
        if (r0 < rows_valid) {
            const float* p = &A[(size_t)(block_m + r0) * IN_DIM + c0 * 8];
            pv[0] = *(const float4*)p; pv[1] = *(const float4*)(p + 4);
        }
        if (r1 < rows_valid) {
            const float* p = &A[(size_t)(block_m + r1) * IN_DIM + c1 * 8];
            pv[2] = *(const float4*)p; pv[3] = *(const float4*)(p + 4);
        }
    }

    for (int kc = 0; kc < IN_DIM / 32; kc++) {
        // ---- convert prefetched A regs -> fp16 smem tile ----
#pragma unroll
        for (int it = 0; it < 2; it++) {
            float4 v0 = pv[it * 2], v1 = pv[it * 2 + 1];
            uint32_t h0 = pack2h(v0.x, v0.y), h1 = pack2h(v0.z, v0.w);
            uint32_t h2 = pack2h(v1.x, v1.y), h3 = pack2h(v1.z, v1.w);
            *(uint4*)(sA + (it ? doff1 : doff0)) = make_uint4(h0, h1, h2, h3);
        }
        // ---- copy pre-converted B tile (L2 resident) ----
        {
            const uint4* bh = (const uint4*)(g_bhi + kc * 8192);
            uint4* dh = (uint4*)sB;
            dh[tid]       = bh[tid];
            dh[tid + 256] = bh[tid + 256];
        }
        __syncthreads();

        // ---- prefetch next chunk's A (hidden under MMAs) ----
        if (kc + 1 < IN_DIM / 32) {
            const int k0n = (kc + 1) * 32;
            pv[0] = pv[1] = pv[2] = pv[3] = make_float4(0.f, 0.f, 0.f, 0.f);
            if (r0 < rows_valid) {
                const float* p = &A[(size_t)(block_m + r0) * IN_DIM + k0n + c0 * 8];
                pv[0] = *(const float4*)p; pv[1] = *(const float4*)(p + 4);
            }
            if (r1 < rows_valid) {
                const float* p = &A[(size_t)(block_m + r1) * IN_DIM + k0n + c1 * 8];
                pv[2] = *(const float4*)p; pv[3] = *(const float4*)(p + 4);
            }
        }

#pragma unroll
        for (int ks = 0; ks < 2; ks++) {
            uint32_t ah[2][4], bb[4][4];
#pragma unroll
            for (int i = 0; i < 2; i++) {
                uint32_t row = a_row + i * 16u;
                uint32_t chunk = (uint32_t)(ks * 2) + a_half;
                uint32_t o = row * 64u + ((chunk ^ a_sw) << 4);
                ldm_x4(ah[i], uA + o);
            }
#pragma unroll
            for (int j = 0; j < 4; j++) {
                uint32_t row = b_row + j * 16u;
                uint32_t chunk = (uint32_t)(ks * 2) + b_half;
                uint32_t o = row * 64u + ((chunk ^ b_sw) << 4);
                ldm_x4(bb[j], uB + o);
            }
#pragma unroll
            for (int i = 0; i < 2; i++)
#pragma unroll
                for (int jf = 0; jf < 8; jf++)
                    mma_fp16(acc[i][jf], ah[i], &bb[jf >> 1][(jf & 1) * 2]);
        }
        __syncthreads();
    }

    float rs1[4] = {0.f, 0.f, 0.f, 0.f}, rs2[4] = {0.f, 0.f, 0.f, 0.f};
#pragma unroll
    for (int i = 0; i < 2; i++)
#pragma unroll
        for (int jf = 0; jf < 8; jf++) {
            int n0 = wn * 64 + jf * 8 + (lane & 3) * 2;
            float a1x = __ldg(&Wa[n0]),            a1y = __ldg(&Wa[n0 + 1]);
            float a2x = __ldg(&Wa[OUT_DIM + n0]),  a2y = __ldg(&Wa[OUT_DIM + n0 + 1]);
#pragma unroll
            for (int hh = 0; hh < 2; hh++) {
                float v0 = acc[i][jf][hh * 2], v1 = acc[i][jf][hh * 2 + 1];
                int m = block_m + wm * 32 + i * 16 + hh * 8 + (lane >> 2);
                if (m < M)
                    *(uint32_t*)&g_z[(size_t)m * OUT_DIM + n0] = pack2h(v0, v1);
                rs1[i * 2 + hh] += v0 * a1x + v1 * a1y;
                rs2[i * 2 + hh] += v0 * a2x + v1 * a2y;
            }
        }
#pragma unroll
    for (int k = 0; k < 4; k++) {
        rs1[k] += __shfl_xor_sync(0xffffffffu, rs1[k], 1);
        rs1[k] += __shfl_xor_sync(0xffffffffu, rs1[k], 2);
        rs2[k] += __shfl_xor_sync(0xffffffffu, rs2[k], 1);
        rs2[k] += __shfl_xor_sync(0xffffffffu, rs2[k], 2);
    }
    // cross-warp (wn) reduction via smem, then plain stores
    float* sred1 = (float*)sA;     // 128 floats
    float* sred2 = (float*)sB;     // 128 floats
    if (wn == 1 && (lane & 3) == 0) {
#pragma unroll
        for (int k = 0; k < 4; k++) {
            int r = wm * 32 + (k >> 1) * 16 + (k & 1) * 8 + (lane >> 2);
            sred1[r] = rs1[k];
            sred2[r] = rs2[k];
        }
    }
    __syncthreads();
    if (wn == 0 && (lane & 3) == 0) {
#pragma unroll
        for (int k = 0; k < 4; k++) {
            int r = wm * 32 + (k >> 1) * 16 + (k & 1) * 8 + (lane >> 2);
            int m = block_m + r;
            if (m < M) {
                g_s1[m] = rs1[k] + sred1[r];
                g_s2[m] = rs2[k] + sred2[r];
            }
        }
    }
}

// ---- histogram of dst: 8 edges per thread (vectorized, MLP=2x int4) ----
__global__ __launch_bounds__(256) void hist_kernel(const int* __restrict__ dst, int E) {
    int base = (blockIdx.x * blockDim.x + threadIdx.x) * 8;
    if (base + 8 <= E) {
        int4 d0 = *(const int4*)&dst[base];
        int4 d1 = *(const int4*)&dst[base + 4];
        atomicAdd(&g_cnt[d0.x], 1u); atomicAdd(&g_cnt[d0.y], 1u);
        atomicAdd(&g_cnt[d0.z], 1u); atomicAdd(&g_cnt[d0.w], 1u);
        atomicAdd(&g_cnt[d1.x], 1u); atomicAdd(&g_cnt[d1.y], 1u);
        atomicAdd(&g_cnt[d1.z], 1u); atomicAdd(&g_cnt[d1.w], 1u);
    } else {
        for (int i = base; i < E; i++) atomicAdd(&g_cnt[dst[i]], 1u);
    }
}

// ---- scan phase 1: per-block tile reduction (coalesced) ----
__global__ __launch_bounds__(1024) void scan_part1() {
    __shared__ unsigned ws[32];
    const int tid = threadIdx.x, lane = tid & 31, wid = tid >> 5;
    int i = blockIdx.x * 1024 + tid;
    unsigned x = (i < NWORDS) ? g_cnt[i] : 0u;
#pragma unroll
    for (int o = 16; o > 0; o >>= 1) x += __shfl_xor_sync(0xffffffffu, x, o);
    if (lane == 0) ws[wid] = x;
    __syncthreads();
    if (wid == 0) {
        unsigned s = ws[lane];
#pragma unroll
        for (int o = 16; o > 0; o >>= 1) s += __shfl_xor_sync(0xffffffffu, s, o);
        if (lane == 0) g_bsum[blockIdx.x] = s;
    }
}

// ---- scan phase 2 (fused): each block scans block sums + its tile ----
__global__ __launch_bounds__(1024) void scan_part3() {
    __shared__ unsigned ws[32];
    __shared__ unsigned s_boff;
    const int tid = threadIdx.x, lane = tid & 31, wid = tid >> 5;

    if (wid == 0) {
        unsigned acc = 0u;
#pragma unroll
        for (int seg = 0; seg < (SCAN_BLOCKS + 31) / 32; seg++) {
            int j = seg * 32 + lane;
            unsigned v = (j < SCAN_BLOCKS) ? g_bsum[j] : 0u;
            unsigned inc = v;
#pragma unroll
            for (int o = 1; o < 32; o <<= 1) {
                unsigned y = __shfl_up_sync(0xffffffffu, inc, o);
                if (lane >= o) inc += y;
            }
            if (j == (int)blockIdx.x) s_boff = acc + inc - v;
            acc += __shfl_sync(0xffffffffu, inc, 31);
        }
    }

    int i = blockIdx.x * 1024 + tid;
    unsigned x = (i < NWORDS) ? g_cnt[i] : 0u;
    unsigned inc = x;
#pragma unroll
    for (int o = 1; o < 32; o <<= 1) {
        unsigned y = __shfl_up_sync(0xffffffffu, inc, o);
        if (lane >= o) inc += y;
    }
    if (lane == 31) ws[wid] = inc;
    __syncthreads();
    if (wid == 0) {
        unsigned s = ws[lane];
#pragma unroll
        for (int o = 1; o < 32; o <<= 1) {
            unsigned y = __shfl_up_sync(0xffffffffu, s, o);
            if (lane >= o) s += y;
        }
        ws[lane] = s;
    }
    __syncthreads();
    unsigned val = inc + (wid > 0 ? ws[wid - 1] : 0u) + s_boff;
    if (i < NWORDS) g_off[i + 1] = val;
    if (i == 0) g_off[0] = 0u;
}

// ---- build grouped edge arrays: 1 edge/thread (occupancy hides latency) ----
__global__ __launch_bounds__(256) void build_kernel(
    const int* __restrict__ src, const int* __restrict__ dst, int E)
{
    int i = blockIdx.x * blockDim.x + threadIdx.x;
    if (i >= E) return;
    int s = src[i], d = dst[i];
    float e = g_s1[s] + g_s2[d];
    e = (e > 0.0f) ? e : 0.01f * e;      // leaky_relu(0.01)
    if (e == 0.0f) e = -1000.0f;         // DGL zero-mask emulation
    unsigned pos = g_off[d] + atomicAdd(&g_cnt2[d], 1u);
    g_esrc[pos] = s;
    g_eval[pos] = e;
}

// ---- aggregate: warp per dst; softmax + weighted sum, single write ----
__global__ __launch_bounds__(256) void aggregate_kernel(float* __restrict__ out) {
    int d    = (blockIdx.x * blockDim.x + threadIdx.x) >> 5;
    int lane = threadIdx.x & 31;
    if (d >= NWORDS) return;
    int b = (int)g_off[d], eend = (int)g_off[d + 1];

    float mx = -1e30f;
    for (int i = b + lane; i < eend; i += 32) mx = fmaxf(mx, g_eval[i]);
#pragma unroll
    for (int o = 16; o > 0; o >>= 1)
        mx = fmaxf(mx, __shfl_xor_sync(0xffffffffu, mx, o));

    float4 acc = make_float4(0.f, 0.f, 0.f, 0.f);
    float denom = 0.f;
    int i = b;
    for (; i + 3 < eend; i += 4) {
        float e0 = g_eval[i],     e1 = g_eval[i + 1];
        float e2 = g_eval[i + 2], e3 = g_eval[i + 3];
        int   s0 = g_esrc[i],     s1 = g_esrc[i + 1];
        int   s2 = g_esrc[i + 2], s3 = g_esrc[i + 3];
        float4 z0 = ldz4(s0, lane), z1 = ldz4(s1, lane);
        float4 z2 = ldz4(s2, lane), z3 = ldz4(s3, lane);
        float x0 = __expf(e0 - mx), x1 = __expf(e1 - mx);
        float x2 = __expf(e2 - mx), x3 = __expf(e3 - mx);
        denom += (x0 + x1) + (x2 + x3);
        acc.x += x0 * z0.x + x1 * z1.x + x2 * z2.x + x3 * z3.x;
        acc.y += x0 * z0.y + x1 * z1.y + x2 * z2.y + x3 * z3.y;
        acc.z += x0 * z0.z + x1 * z1.z + x2 * z2.z + x3 * z3.z;
        acc.w += x0 * z0.w + x1 * z1.w + x2 * z2.w + x3 * z3.w;
    }
    for (; i < eend; i++) {
        float e0 = g_eval[i];
        int   s0 = g_esrc[i];
        float4 z0 = ldz4(s0, lane);
        float x0 = __expf(e0 - mx);
        denom += x0;
        acc.x += x0 * z0.x; acc.y += x0 * z0.y;
        acc.z += x0 * z0.z; acc.w += x0 * z0.w;
    }
    float inv = (eend > b) ? 1.0f / denom : 0.0f;
    *(float4*)&out[(size_t)d * OUT_DIM + lane * 4] =
        make_float4(acc.x * inv, acc.y * inv, acc.z * inv, acc.w * inv);
}

extern "C" void kernel_launch(void* const* d_in, const int* in_sizes, int n_in,
                              void* d_out, int out_size) {
    const float* h   = (const float*)d_in[0];
    const int*   src = (const int*)d_in[1];
    const int*   dst = (const int*)d_in[2];
    const float* Wfc = (const float*)d_in[3];
    const float* Wa  = (const float*)d_in[4];
    float* out = (float*)d_out;

    int M = in_sizes[0] / IN_DIM;   // 100000
    int E = in_sizes[1];            // 500000

    // fork-join: hist/scan chain overlaps convertB + GEMM
    cudaStream_t s2;
    cudaStreamCreateWithFlags(&s2, cudaStreamNonBlocking);
    cudaEvent_t ev_fork, ev_join;
    cudaEventCreateWithFlags(&ev_fork, cudaEventDisableTiming);
    cudaEventCreateWithFlags(&ev_join, cudaEventDisableTiming);

    cudaEventRecord(ev_fork, 0);

    // side stream: counter init + histogram + scan
    cudaStreamWaitEvent(s2, ev_fork, 0);
    init_cnt_kernel<<<(NWORDS + 255) / 256, 256, 0, s2>>>();
    hist_kernel<<<(E + 8 * 256 - 1) / (8 * 256), 256, 0, s2>>>(dst, E);
    scan_part1<<<SCAN_BLOCKS, 1024, 0, s2>>>();
    scan_part3<<<SCAN_BLOCKS, 1024, 0, s2>>>();
    cudaEventRecord(ev_join, s2);

    // main stream: B convert + GEMM (bulk of the work)
    convert_b_kernel<<<(128 * 256 + 255) / 256, 256>>>(Wfc);
    gemm_mma<<<(M + 127) / 128, 256>>>(h, Wa, M);

    cudaStreamWaitEvent(0, ev_join, 0);
    build_kernel<<<(E + 255) / 256, 256>>>(src, dst, E);
    aggregate_kernel<<<((NWORDS * 32) + 255) / 256, 256>>>(out);

    cudaEventDestroy(ev_fork);
    cudaEventDestroy(ev_join);
    cudaStreamDestroy(s2);
}

// round 16
// speedup vs baseline: 1.0671x; 1.0671x over previous
#include <cuda_runtime.h>
#include <cuda_fp16.h>
#include <cstdint>

#define NMAX 100000
#define NWORDS 50000
#define EMAX 500000
#define IN_DIM 256
#define OUT_DIM 128

// ---- scratch (static device globals; no allocation) ----
__device__ __half   g_z[(size_t)NMAX * OUT_DIM];   // fc output z [N,128] (fp16)
__device__ float    g_s1[NMAX];                    // z . a1
__device__ float    g_s2[NMAX];                    // z . a2
__device__ unsigned g_cnt[NWORDS];                 // per-dst edge counts
__device__ unsigned g_cnt2[NWORDS];                // scatter cursors
__device__ unsigned g_off[NWORDS + 1];             // CSR offsets
__device__ int      g_esrc[EMAX];                  // grouped edge src ids
__device__ float    g_eval[EMAX];                  // grouped edge scores
// pre-converted B (fp16) in swizzled tile layout: [kchunk][128 rows x 64 B]
__device__ __align__(16) uint8_t g_bhi[8 * 8192];

#define SCAN_BLOCKS ((NWORDS + 1023) / 1024)       // 49
__device__ unsigned g_bsum[SCAN_BLOCKS];

__device__ __forceinline__ uint32_t smem_u32(const void* p) {
    uint32_t a;
    asm("{ .reg .u64 t; cvta.to.shared.u64 t, %1; cvt.u32.u64 %0, t; }" : "=r"(a) : "l"(p));
    return a;
}
__device__ __forceinline__ void ldm_x4(uint32_t* r, uint32_t addr) {
    asm volatile("ldmatrix.sync.aligned.m8n8.x4.shared.b16 {%0,%1,%2,%3}, [%4];"
                 : "=r"(r[0]), "=r"(r[1]), "=r"(r[2]), "=r"(r[3]) : "r"(addr));
}
__device__ __forceinline__ void mma_fp16(float* c, const uint32_t* a, const uint32_t* b) {
    asm volatile(
        "mma.sync.aligned.m16n8k16.row.col.f32.f16.f16.f32 "
        "{%0,%1,%2,%3}, {%4,%5,%6,%7}, {%8,%9}, {%0,%1,%2,%3};"
        : "+f"(c[0]), "+f"(c[1]), "+f"(c[2]), "+f"(c[3])
        : "r"(a[0]), "r"(a[1]), "r"(a[2]), "r"(a[3]), "r"(b[0]), "r"(b[1]));
}
__device__ __forceinline__ uint32_t pack2h(float a, float b) {
    __half2 t = __floats2half2_rn(a, b);
    return *reinterpret_cast<uint32_t*>(&t);
}
// tile byte offset: row pitch 64B (32 fp16), 16B chunks xor-swizzled
__device__ __forceinline__ uint32_t tile_off(uint32_t row, uint32_t chunk) {
    return row * 64u + ((chunk ^ ((row >> 1) & 3u)) << 4);
}

// ---- side-stream init: zero histogram counters ----
__global__ __launch_bounds__(256) void init_cnt_kernel() {
    int i = blockIdx.x * blockDim.x + threadIdx.x;
    if (i < NWORDS) g_cnt[i] = 0u;
}

// ---- main-stream: one-time B fp16 convert into swizzled layout ----
__global__ __launch_bounds__(256) void convert_b_kernel(const float* __restrict__ B) {
    int i = blockIdx.x * blockDim.x + threadIdx.x;   // 0..32767
    if (i >= 128 * 256) return;
    int row = i >> 8, col = i & 255;
    int kc = col >> 5, c = col & 31;
    uint32_t off = (uint32_t)kc * 8192u + tile_off((uint32_t)row, (uint32_t)(c >> 3)) + (c & 7) * 2;
    *(__half*)(g_bhi + off) = __float2half_rn(B[i]);
}

// ==========================================================================
// fp16 single-product GEMM via mma.sync: z = fp16(A) @ fp16(B)^T, fp32 acc.
// z stored as fp16; s1/s2 from fp32 acc via smem reduction (no atomics).
// ==========================================================================
__global__ void __launch_bounds__(256, 2)
gemm_mma(const float* __restrict__ A, const float* __restrict__ Wa, int M)
{
    __shared__ __align__(128) uint8_t sA[128 * 64];
    __shared__ __align__(128) uint8_t sB[128 * 64];

    const int tid  = threadIdx.x;
    const int lane = tid & 31;
    const int w    = tid >> 5;
    const int wm   = w & 3;
    const int wn   = w >> 2;
    const int block_m = blockIdx.x * 128;
    int rows_valid = M - block_m; if (rows_valid > 128) rows_valid = 128;

    const uint32_t uA = smem_u32(sA);
    const uint32_t uB = smem_u32(sB);

    const uint32_t a_row  = wm * 32u + (lane & 15);
    const uint32_t a_half = (uint32_t)lane >> 4;
    const uint32_t a_sw   = (a_row >> 1) & 3u;
    const uint32_t b_row  = wn * 64u + (lane & 7) + (((uint32_t)lane >> 4) << 3);
    const uint32_t b_half = ((uint32_t)lane >> 3) & 1u;
    const uint32_t b_sw   = (b_row >> 1) & 3u;

    const int r0 = tid >> 2,         c0 = tid & 3;
    const int r1 = (tid + 256) >> 2, c1 = (tid + 256) & 3;
    const uint32_t doff0 = tile_off((uint32_t)r0, (uint32_t)c0);
    const uint32_t doff1 = tile_off((uint32_t)r1, (uint32_t)c1);

    float acc[2][8][4];
#pragma unroll
    for (int i = 0; i < 2; i++)
#pragma unroll
        for (int j = 0; j < 8; j++)
#pragma unroll
            for (int r = 0; r < 4; r++) acc[i][j][r] = 0.0f;

    float4 pv[4];
    {
        pv[0] = pv[1] = pv[2] = pv[3] = make_float4(0.f, 0.f, 0.f, 0.f);
        if (r0 < rows_valid) {
            const float* p = &A[(size_t)(block_m + r0) * IN_DIM + c0 * 8];
            pv[0] = *(const float4*)p; pv[1] = *(const float4*)(p + 4);
        }
        if (r1 < rows_valid) {
            const float* p = &A[(size_t)(block_m + r1) * IN_DIM + c1 * 8];
            pv[2] = *(const float4*)p; pv[3] = *(const float4*)(p + 4);
        }
    }

    for (int kc = 0; kc < IN_DIM / 32; kc++) {
        // ---- convert prefetched A regs -> fp16 smem tile ----
#pragma unroll
        for (int it = 0; it < 2; it++) {
            float4 v0 = pv[it * 2], v1 = pv[it * 2 + 1];
            uint32_t h0 = pack2h(v0.x, v0.y), h1 = pack2h(v0.z, v0.w);
            uint32_t h2 = pack2h(v1.x, v1.y), h3 = pack2h(v1.z, v1.w);
            *(uint4*)(sA + (it ? doff1 : doff0)) = make_uint4(h0, h1, h2, h3);
        }
        // ---- copy pre-converted B tile (L2 resident) ----
        {
            const uint4* bh = (const uint4*)(g_bhi + kc * 8192);
            uint4* dh = (uint4*)sB;
            dh[tid]       = bh[tid];
            dh[tid + 256] = bh[tid + 256];
        }
        __syncthreads();

        // ---- prefetch next chunk's A (hidden under MMAs) ----
        if (kc + 1 < IN_DIM / 32) {
            const int k0n = (kc + 1) * 32;
            pv[0] = pv[1] = pv[2] = pv[3] = make_float4(0.f, 0.f, 0.f, 0.f);
            if (r0 < rows_valid) {
                const float* p = &A[(size_t)(block_m + r0) * IN_DIM + k0n + c0 * 8];
                pv[0] = *(const float4*)p; pv[1] = *(const float4*)(p + 4);
            }
            if (r1 < rows_valid) {
                const float* p = &A[(size_t)(block_m + r1) * IN_DIM + k0n + c1 * 8];
                pv[2] = *(const float4*)p; pv[3] = *(const float4*)(p + 4);
            }
        }

#pragma unroll
        for (int ks = 0; ks < 2; ks++) {
            uint32_t ah[2][4], bb[4][4];
#pragma unroll
            for (int i = 0; i < 2; i++) {
                uint32_t row = a_row + i * 16u;
                uint32_t chunk = (uint32_t)(ks * 2) + a_half;
                uint32_t o = row * 64u + ((chunk ^ a_sw) << 4);
                ldm_x4(ah[i], uA + o);
            }
#pragma unroll
            for (int j = 0; j < 4; j++) {
                uint32_t row = b_row + j * 16u;
                uint32_t chunk = (uint32_t)(ks * 2) + b_half;
                uint32_t o = row * 64u + ((chunk ^ b_sw) << 4);
                ldm_x4(bb[j], uB + o);
            }
#pragma unroll
            for (int i = 0; i < 2; i++)
#pragma unroll
                for (int jf = 0; jf < 8; jf++)
                    mma_fp16(acc[i][jf], ah[i], &bb[jf >> 1][(jf & 1) * 2]);
        }
        __syncthreads();
    }

    float rs1[4] = {0.f, 0.f, 0.f, 0.f}, rs2[4] = {0.f, 0.f, 0.f, 0.f};
#pragma unroll
    for (int i = 0; i < 2; i++)
#pragma unroll
        for (int jf = 0; jf < 8; jf++) {
            int n0 = wn * 64 + jf * 8 + (lane & 3) * 2;
            float a1x = __ldg(&Wa[n0]),            a1y = __ldg(&Wa[n0 + 1]);
            float a2x = __ldg(&Wa[OUT_DIM + n0]),  a2y = __ldg(&Wa[OUT_DIM + n0 + 1]);
#pragma unroll
            for (int hh = 0; hh < 2; hh++) {
                float v0 = acc[i][jf][hh * 2], v1 = acc[i][jf][hh * 2 + 1];
                int m = block_m + wm * 32 + i * 16 + hh * 8 + (lane >> 2);
                if (m < M)
                    *(uint32_t*)&g_z[(size_t)m * OUT_DIM + n0] = pack2h(v0, v1);
                rs1[i * 2 + hh] += v0 * a1x + v1 * a1y;
                rs2[i * 2 + hh] += v0 * a2x + v1 * a2y;
            }
        }
#pragma unroll
    for (int k = 0; k < 4; k++) {
        rs1[k] += __shfl_xor_sync(0xffffffffu, rs1[k], 1);
        rs1[k] += __shfl_xor_sync(0xffffffffu, rs1[k], 2);
        rs2[k] += __shfl_xor_sync(0xffffffffu, rs2[k], 1);
        rs2[k] += __shfl_xor_sync(0xffffffffu, rs2[k], 2);
    }
    // cross-warp (wn) reduction via smem, then plain stores
    float* sred1 = (float*)sA;     // 128 floats
    float* sred2 = (float*)sB;     // 128 floats
    if (wn == 1 && (lane & 3) == 0) {
#pragma unroll
        for (int k = 0; k < 4; k++) {
            int r = wm * 32 + (k >> 1) * 16 + (k & 1) * 8 + (lane >> 2);
            sred1[r] = rs1[k];
            sred2[r] = rs2[k];
        }
    }
    __syncthreads();
    if (wn == 0 && (lane & 3) == 0) {
#pragma unroll
        for (int k = 0; k < 4; k++) {
            int r = wm * 32 + (k >> 1) * 16 + (k & 1) * 8 + (lane >> 2);
            int m = block_m + r;
            if (m < M) {
                g_s1[m] = rs1[k] + sred1[r];
                g_s2[m] = rs2[k] + sred2[r];
            }
        }
    }
}

// ---- histogram of dst: 8 edges per thread (vectorized, MLP=2x int4) ----
__global__ __launch_bounds__(256) void hist_kernel(const int* __restrict__ dst, int E) {
    int base = (blockIdx.x * blockDim.x + threadIdx.x) * 8;
    if (base + 8 <= E) {
        int4 d0 = *(const int4*)&dst[base];
        int4 d1 = *(const int4*)&dst[base + 4];
        atomicAdd(&g_cnt[d0.x], 1u); atomicAdd(&g_cnt[d0.y], 1u);
        atomicAdd(&g_cnt[d0.z], 1u); atomicAdd(&g_cnt[d0.w], 1u);
        atomicAdd(&g_cnt[d1.x], 1u); atomicAdd(&g_cnt[d1.y], 1u);
        atomicAdd(&g_cnt[d1.z], 1u); atomicAdd(&g_cnt[d1.w], 1u);
    } else {
        for (int i = base; i < E; i++) atomicAdd(&g_cnt[dst[i]], 1u);
    }
}

// ---- scan phase 1: per-block tile reduction (coalesced) ----
__global__ __launch_bounds__(1024) void scan_part1() {
    __shared__ unsigned ws[32];
    const int tid = threadIdx.x, lane = tid & 31, wid = tid >> 5;
    int i = blockIdx.x * 1024 + tid;
    unsigned x = (i < NWORDS) ? g_cnt[i] : 0u;
#pragma unroll
    for (int o = 16; o > 0; o >>= 1) x += __shfl_xor_sync(0xffffffffu, x, o);
    if (lane == 0) ws[wid] = x;
    __syncthreads();
    if (wid == 0) {
        unsigned s = ws[lane];
#pragma unroll
        for (int o = 16; o > 0; o >>= 1) s += __shfl_xor_sync(0xffffffffu, s, o);
        if (lane == 0) g_bsum[blockIdx.x] = s;
    }
}

// ---- scan phase 2 (fused): block sums + tile scan + cursor zeroing ----
__global__ __launch_bounds__(1024) void scan_part3() {
    __shared__ unsigned ws[32];
    __shared__ unsigned s_boff;
    const int tid = threadIdx.x, lane = tid & 31, wid = tid >> 5;

    if (wid == 0) {
        unsigned acc = 0u;
#pragma unroll
        for (int seg = 0; seg < (SCAN_BLOCKS + 31) / 32; seg++) {
            int j = seg * 32 + lane;
            unsigned v = (j < SCAN_BLOCKS) ? g_bsum[j] : 0u;
            unsigned inc = v;
#pragma unroll
            for (int o = 1; o < 32; o <<= 1) {
                unsigned y = __shfl_up_sync(0xffffffffu, inc, o);
                if (lane >= o) inc += y;
            }
            if (j == (int)blockIdx.x) s_boff = acc + inc - v;
            acc += __shfl_sync(0xffffffffu, inc, 31);
        }
    }

    int i = blockIdx.x * 1024 + tid;
    unsigned x = (i < NWORDS) ? g_cnt[i] : 0u;
    unsigned inc = x;
#pragma unroll
    for (int o = 1; o < 32; o <<= 1) {
        unsigned y = __shfl_up_sync(0xffffffffu, inc, o);
        if (lane >= o) inc += y;
    }
    if (lane == 31) ws[wid] = inc;
    __syncthreads();
    if (wid == 0) {
        unsigned s = ws[lane];
#pragma unroll
        for (int o = 1; o < 32; o <<= 1) {
            unsigned y = __shfl_up_sync(0xffffffffu, s, o);
            if (lane >= o) s += y;
        }
        ws[lane] = s;
    }
    __syncthreads();
    unsigned val = inc + (wid > 0 ? ws[wid - 1] : 0u) + s_boff;
    if (i < NWORDS) {
        g_off[i + 1] = val;
        g_cnt2[i] = 0u;       // zero scatter cursors here (build runs after)
    }
    if (i == 0) g_off[0] = 0u;
}

// ---- build grouped edge arrays: 1 edge/thread (occupancy hides latency) ----
__global__ __launch_bounds__(256) void build_kernel(
    const int* __restrict__ src, const int* __restrict__ dst, int E)
{
    int i = blockIdx.x * blockDim.x + threadIdx.x;
    if (i >= E) return;
    int s = src[i], d = dst[i];
    float e = g_s1[s] + g_s2[d];
    e = (e > 0.0f) ? e : 0.01f * e;      // leaky_relu(0.01)
    if (e == 0.0f) e = -1000.0f;         // DGL zero-mask emulation
    unsigned pos = g_off[d] + atomicAdd(&g_cnt2[d], 1u);
    g_esrc[pos] = s;
    g_eval[pos] = e;
}

// ---- aggregate: warp per dst; half-warp per edge (2 edges per warp-instr) ----
__global__ __launch_bounds__(256) void aggregate_kernel(float* __restrict__ out) {
    int d    = (blockIdx.x * blockDim.x + threadIdx.x) >> 5;
    int lane = threadIdx.x & 31;
    if (d >= NWORDS) return;
    int b = (int)g_off[d], eend = (int)g_off[d + 1];

    const int half = lane >> 4;      // 0 or 1
    const int sub  = lane & 15;      // 0..15, covers 8 cols each

    // segment max (lane-parallel, coalesced)
    float mx = -1e30f;
    for (int i = b + lane; i < eend; i += 32) mx = fmaxf(mx, g_eval[i]);
#pragma unroll
    for (int o = 16; o > 0; o >>= 1)
        mx = fmaxf(mx, __shfl_xor_sync(0xffffffffu, mx, o));

    float acc[8] = {0.f, 0.f, 0.f, 0.f, 0.f, 0.f, 0.f, 0.f};
    float denom = 0.f;
    // each half-warp walks alternating edges; 2 edges per warp instruction,
    // unrolled 2x per half -> 4 edges in flight
    int i = b + half;
    for (; i + 2 < eend; i += 4) {
        int   s0 = g_esrc[i],   s1 = g_esrc[i + 2];
        float e0 = g_eval[i],   e1 = g_eval[i + 2];
        uint4 q0 = __ldg((const uint4*)&g_z[(size_t)s0 * OUT_DIM + sub * 8]);
        uint4 q1 = __ldg((const uint4*)&g_z[(size_t)s1 * OUT_DIM + sub * 8]);
        float x0 = __expf(e0 - mx), x1 = __expf(e1 - mx);
        denom += x0 + x1;
        float2 f;
        f = __half22float2(*(__half2*)&q0.x); acc[0] += x0 * f.x; acc[1] += x0 * f.y;
        f = __half22float2(*(__half2*)&q0.y); acc[2] += x0 * f.x; acc[3] += x0 * f.y;
        f = __half22float2(*(__half2*)&q0.z); acc[4] += x0 * f.x; acc[5] += x0 * f.y;
        f = __half22float2(*(__half2*)&q0.w); acc[6] += x0 * f.x; acc[7] += x0 * f.y;
        f = __half22float2(*(__half2*)&q1.x); acc[0] += x1 * f.x; acc[1] += x1 * f.y;
        f = __half22float2(*(__half2*)&q1.y); acc[2] += x1 * f.x; acc[3] += x1 * f.y;
        f = __half22float2(*(__half2*)&q1.z); acc[4] += x1 * f.x; acc[5] += x1 * f.y;
        f = __half22float2(*(__half2*)&q1.w); acc[6] += x1 * f.x; acc[7] += x1 * f.y;
    }
    if (i < eend) {
        int   s0 = g_esrc[i];
        float e0 = g_eval[i];
        uint4 q0 = __ldg((const uint4*)&g_z[(size_t)s0 * OUT_DIM + sub * 8]);
        float x0 = __expf(e0 - mx);
        denom += x0;
        float2 f;
        f = __half22float2(*(__half2*)&q0.x); acc[0] += x0 * f.x; acc[1] += x0 * f.y;
        f = __half22float2(*(__half2*)&q0.y); acc[2] += x0 * f.x; acc[3] += x0 * f.y;
        f = __half22float2(*(__half2*)&q0.z); acc[4] += x0 * f.x; acc[5] += x0 * f.y;
        f = __half22float2(*(__half2*)&q0.w); acc[6] += x0 * f.x; acc[7] += x0 * f.y;
    }
    // combine the two half-warps (same column slice, disjoint edges)
#pragma unroll
    for (int k = 0; k < 8; k++)
        acc[k] += __shfl_xor_sync(0xffffffffu, acc[k], 16);
    denom += __shfl_xor_sync(0xffffffffu, denom, 16);

    float inv = (eend > b) ? 1.0f / denom : 0.0f;
    // every lane writes one float4: cols sub*8 + half*4 .. +3
    float4 v = make_float4(acc[half * 4 + 0] * inv, acc[half * 4 + 1] * inv,
                           acc[half * 4 + 2] * inv, acc[half * 4 + 3] * inv);
    *(float4*)&out[(size_t)d * OUT_DIM + sub * 8 + half * 4] = v;
}

extern "C" void kernel_launch(void* const* d_in, const int* in_sizes, int n_in,
                              void* d_out, int out_size) {
    const float* h   = (const float*)d_in[0];
    const int*   src = (const int*)d_in[1];
    const int*   dst = (const int*)d_in[2];
    const float* Wfc = (const float*)d_in[3];
    const float* Wa  = (const float*)d_in[4];
    float* out = (float*)d_out;

    int M = in_sizes[0] / IN_DIM;   // 100000
    int E = in_sizes[1];            // 500000

    // fork-join: hist/scan chain overlaps convertB + GEMM
    cudaStream_t s2;
    cudaStreamCreateWithFlags(&s2, cudaStreamNonBlocking);
    cudaEvent_t ev_fork, ev_join;
    cudaEventCreateWithFlags(&ev_fork, cudaEventDisableTiming);
    cudaEventCreateWithFlags(&ev_join, cudaEventDisableTiming);

    cudaEventRecord(ev_fork, 0);

    // side stream: counter init + histogram + scan
    cudaStreamWaitEvent(s2, ev_fork, 0);
    init_cnt_kernel<<<(NWORDS + 255) / 256, 256, 0, s2>>>();
    hist_kernel<<<(E + 8 * 256 - 1) / (8 * 256), 256, 0, s2>>>(dst, E);
    scan_part1<<<SCAN_BLOCKS, 1024, 0, s2>>>();
    scan_part3<<<SCAN_BLOCKS, 1024, 0, s2>>>();
    cudaEventRecord(ev_join, s2);

    // main stream: B convert + GEMM (bulk of the work)
    convert_b_kernel<<<(128 * 256 + 255) / 256, 256>>>(Wfc);
    gemm_mma<<<(M + 127) / 128, 256>>>(h, Wa, M);

    cudaStreamWaitEvent(0, ev_join, 0);
    build_kernel<<<(E + 255) / 256, 256>>>(src, dst, E);
    aggregate_kernel<<<((NWORDS * 32) + 255) / 256, 256>>>(out);

    cudaEventDestroy(ev_fork);
    cudaEventDestroy(ev_join);
    cudaStreamDestroy(s2);
}